// round 15
// baseline (speedup 1.0000x reference)
#include <cuda_runtime.h>
#include <cuda_fp16.h>
#include <cstdint>

#define B_   2
#define T_   4096
#define D_   512
#define H_   8
#define HD_  64
#define M_   (B_ * T_)
#define N3_  (3 * D_)

__device__ __align__(256) __half g_hx[M_ * D_];
__device__ __align__(256) __half g_hwq[N3_ * D_];
__device__ __align__(256) __half g_hwo[D_ * D_];
__device__ __align__(256) __half g_qkvh[M_ * N3_];
__device__ __align__(256) __half g_atth[M_ * D_];

#define QSCALE 0.180336879f   /* 0.125 * log2(e) */

// ---------------------------------------------------------------------------
// helpers
// ---------------------------------------------------------------------------
__device__ __forceinline__ unsigned cvt_h2(float lo, float hi) {
    unsigned r;
    asm("cvt.rn.f16x2.f32 %0, %1, %2;" : "=r"(r) : "f"(hi), "f"(lo));
    return r;
}
__device__ __forceinline__ float ex2(float x) {
    float r;
    asm("ex2.approx.ftz.f32 %0, %1;" : "=f"(r) : "f"(x));
    return r;
}
__device__ __forceinline__ void mma_f16(float d[4], const unsigned a[4],
                                        const unsigned b[2]) {
    asm volatile(
        "mma.sync.aligned.m16n8k16.row.col.f32.f16.f16.f32 "
        "{%0,%1,%2,%3}, {%4,%5,%6,%7}, {%8,%9}, {%0,%1,%2,%3};\n"
        : "+f"(d[0]), "+f"(d[1]), "+f"(d[2]), "+f"(d[3])
        : "r"(a[0]), "r"(a[1]), "r"(a[2]), "r"(a[3]), "r"(b[0]), "r"(b[1]));
}
__device__ __forceinline__ uint32_t smem_u32(const void* p) {
    uint32_t a;
    asm("{ .reg .u64 t; cvta.to.shared.u64 t, %1; cvt.u32.u64 %0, t; }"
        : "=r"(a) : "l"(p));
    return a;
}
__device__ __forceinline__ void ldsm_x4(unsigned r[4], uint32_t addr) {
    asm volatile("ldmatrix.sync.aligned.m8n8.x4.shared.b16 {%0,%1,%2,%3}, [%4];"
                 : "=r"(r[0]), "=r"(r[1]), "=r"(r[2]), "=r"(r[3]) : "r"(addr));
}
__device__ __forceinline__ void cp16(uint32_t dst, const void* src) {
    asm volatile("cp.async.cg.shared.global [%0], [%1], 16;"
                 :: "r"(dst), "l"(src) : "memory");
}
#define CP_COMMIT() asm volatile("cp.async.commit_group;" ::: "memory")
#define CP_WAIT1()  asm volatile("cp.async.wait_group 1;" ::: "memory")
#define CP_WAIT0()  asm volatile("cp.async.wait_group 0;" ::: "memory")

// ---------------------------------------------------------------------------
// fp32 -> f16 convert (grid-stride)
// ---------------------------------------------------------------------------
__global__ void cvt_f2h_kernel(const float* __restrict__ src,
                               __half* __restrict__ dst, int n4) {
    const int stride = gridDim.x * blockDim.x;
    for (int i = blockIdx.x * blockDim.x + threadIdx.x; i < n4; i += stride) {
        const float4 v = reinterpret_cast<const float4*>(src)[i];
        unsigned* p = reinterpret_cast<unsigned*>(dst) + 2 * i;
        p[0] = cvt_h2(v.x, v.y);
        p[1] = cvt_h2(v.z, v.w);
    }
}

// ---------------------------------------------------------------------------
// NT GEMM, f16, cp.async 2-stage, BK=64, fragments via ldmatrix.x4.
// BM=128, BN=128, 8 warps (4x2), warp tile 32x64, 64 mmas/iter.
// smem rows stride 72 halfs (144B): ldmatrix 8-row matrices conflict-free.
// ---------------------------------------------------------------------------
#define GST2   72
#define GA_H   (128 * GST2)
#define GBUF_H (2 * GA_H)
#define GEMM_SMEM (2 * GBUF_H * 2)    // 73728 B

__device__ __forceinline__ void gemm_cp_tile_h(uint32_t sbase, int s,
                                               const __half* __restrict__ A,
                                               const __half* __restrict__ Bm,
                                               int m0, int n0, int K, int k0,
                                               int lr, int c) {
    const uint32_t da = sbase + (uint32_t)(s * GBUF_H + lr * GST2 + c * 8) * 2u;
    const uint32_t db = da + (uint32_t)GA_H * 2u;
#pragma unroll
    for (int i = 0; i < 4; ++i) {
        cp16(da + (uint32_t)(i * 32 * GST2) * 2u,
             A + (size_t)(m0 + lr + 32 * i) * K + k0 + c * 8);
        cp16(db + (uint32_t)(i * 32 * GST2) * 2u,
             Bm + (size_t)(n0 + lr + 32 * i) * K + k0 + c * 8);
    }
    CP_COMMIT();
}

template <bool HALF_OUT, bool SCALEQ>
__device__ __forceinline__ void gemm_nt_h16(const __half* __restrict__ A,
                                            const __half* __restrict__ Bm,
                                            void* __restrict__ Cv,
                                            int N, int K) {
    extern __shared__ __half hs[];
    const uint32_t sbase = smem_u32(hs);

    const int tid = threadIdx.x;
    const int w = tid >> 5;
    const int lane = tid & 31;
    const int gid = lane >> 2;
    const int tig = lane & 3;
    const int wm = w >> 1;
    const int wn = w & 1;

    const int m0 = blockIdx.y * 128;
    const int n0 = blockIdx.x * 128;

    const int lr = tid >> 3;
    const int c = tid & 7;

    const int niter = K / 64;

    // ldmatrix lane bases (buffer 0; stage adds GBUF_H*2 bytes)
    // A x4: quadrants by lane>>4 -> k +8 halfs; rows = wm*32 + (lane&15)
    const uint32_t a_u32 = sbase +
        (uint32_t)((wm * 32 + (lane & 15)) * GST2 + ((lane >> 4) << 3)) * 2u;
    // B x4 (two n-tiles): rows = wn*64 + (lane&7) + ((lane>>4)<<3);
    //                     k += 8 halfs for quadrants 1,3 (lane>>3 odd)
    const uint32_t b_u32 = sbase + (uint32_t)GA_H * 2u +
        (uint32_t)((wn * 64 + (lane & 7) + ((lane >> 4) << 3)) * GST2 +
                   (((lane >> 3) & 1) << 3)) * 2u;

    gemm_cp_tile_h(sbase, 0, A, Bm, m0, n0, K, 0, lr, c);
    gemm_cp_tile_h(sbase, 1, A, Bm, m0, n0, K, 64, lr, c);

    float acc[2][8][4] = {};

#pragma unroll 1
    for (int it = 0; it < niter; ++it) {
        const int s = it & 1;
        if (it + 1 < niter) { CP_WAIT1(); } else { CP_WAIT0(); }
        __syncthreads();

        const uint32_t soff = (uint32_t)(s * GBUF_H) * 2u;

#pragma unroll
        for (int ks = 0; ks < 4; ++ks) {
            unsigned aa[2][4], bb[4][4];
#pragma unroll
            for (int mt = 0; mt < 2; ++mt)
                ldsm_x4(aa[mt], a_u32 + soff +
                        (uint32_t)(mt * 16 * GST2 + ks * 16) * 2u);
#pragma unroll
            for (int ntp = 0; ntp < 4; ++ntp)
                ldsm_x4(bb[ntp], b_u32 + soff +
                        (uint32_t)(ntp * 16 * GST2 + ks * 16) * 2u);
#pragma unroll
            for (int mt = 0; mt < 2; ++mt)
#pragma unroll
                for (int ntp = 0; ntp < 4; ++ntp) {
                    unsigned b0[2] = {bb[ntp][0], bb[ntp][1]};
                    unsigned b1[2] = {bb[ntp][2], bb[ntp][3]};
                    mma_f16(acc[mt][2 * ntp],     aa[mt], b0);
                    mma_f16(acc[mt][2 * ntp + 1], aa[mt], b1);
                }
        }

        __syncthreads();
        if (it + 2 < niter)
            gemm_cp_tile_h(sbase, s, A, Bm, m0, n0, K, (it + 2) * 64, lr, c);
    }

#pragma unroll
    for (int mt = 0; mt < 2; ++mt) {
        const int r0 = m0 + wm * 32 + mt * 16 + gid;
#pragma unroll
        for (int nt = 0; nt < 8; ++nt) {
            const int cc = n0 + wn * 64 + nt * 8 + 2 * tig;
            if (HALF_OUT) {
                __half* Ch = reinterpret_cast<__half*>(Cv);
                const float sq = (SCALEQ && cc < 512) ? QSCALE : 1.0f;
                *reinterpret_cast<unsigned*>(Ch + (size_t)r0 * N + cc) =
                    cvt_h2(acc[mt][nt][0] * sq, acc[mt][nt][1] * sq);
                *reinterpret_cast<unsigned*>(Ch + (size_t)(r0 + 8) * N + cc) =
                    cvt_h2(acc[mt][nt][2] * sq, acc[mt][nt][3] * sq);
            } else {
                float* Cf = reinterpret_cast<float*>(Cv);
                *reinterpret_cast<float2*>(Cf + (size_t)r0 * N + cc) =
                    make_float2(acc[mt][nt][0], acc[mt][nt][1]);
                *reinterpret_cast<float2*>(Cf + (size_t)(r0 + 8) * N + cc) =
                    make_float2(acc[mt][nt][2], acc[mt][nt][3]);
            }
        }
    }
}

__global__ void __launch_bounds__(256)
gemm_qkv_kernel() {
    gemm_nt_h16<true, true>(g_hx, g_hwq, g_qkvh, N3_, D_);
}

__global__ void __launch_bounds__(256)
gemm_out_kernel(float* __restrict__ out) {
    gemm_nt_h16<false, false>(g_atth, g_hwo, out, D_, D_);
}

// ---------------------------------------------------------------------------
// Flash attention (causal), f16 mma — R14 structure, now 3 CTAs/SM so the
// MUFU(exp2)/ALU phases of one CTA overlap the tensor phases of the others.
// 128 threads = 4 warps x 32 q-rows, BM=128, BN=64.
// ---------------------------------------------------------------------------
#define QST 40
#define VSTW 36

__global__ void __launch_bounds__(128, 3) flash_f16_kernel() {
    __shared__ unsigned Qs[128 * QST];
    __shared__ unsigned Ks[64 * QST];
    __shared__ unsigned Vs[64 * VSTW];

    const int tid = threadIdx.x;
    const int w = tid >> 5;
    const int lane = tid & 31;
    const int gid = lane >> 2;
    const int tig = lane & 3;

    const int qt = (int)gridDim.y - 1 - (int)blockIdx.y;
    const int q0 = qt * 128;
    const int bh = blockIdx.x;
    const int b = bh >> 3;
    const int h = bh & 7;

    const __half* qptr = g_qkvh + (size_t)b * T_ * N3_ + h * HD_;
    const __half* kptr = qptr + D_;
    const __half* vptr = qptr + 2 * D_;

    const int lr = tid >> 3;          // 0..15
    const int c = tid & 7;            // 8-half d-chunk
    const int pb = 8 * (c >> 1) + (c & 1);

    // ---- stage Q (already scaled f16; permuted copy) ----
#pragma unroll
    for (int i = 0; i < 8; ++i) {
        const int rr = lr + 16 * i;
        const uint4 v = *reinterpret_cast<const uint4*>(
            qptr + (size_t)(q0 + rr) * N3_ + c * 8);
        unsigned* p = Qs + rr * QST + pb;
        p[0] = v.x; p[2] = v.y; p[4] = v.z; p[6] = v.w;
    }

    uint4 kreg[4], vreg[4];
#pragma unroll
    for (int i = 0; i < 4; ++i) {
        kreg[i] = *reinterpret_cast<const uint4*>(kptr + (size_t)(lr + 16 * i) * N3_ + c * 8);
        vreg[i] = *reinterpret_cast<const uint4*>(vptr + (size_t)(lr + 16 * i) * N3_ + c * 8);
    }

    float oc[2][8][4] = {};
    float li[2][2] = {};

    const int rowlo = q0 + w * 32;
    const int niter = 2 * (qt + 1);

    const uint32_t vbase = smem_u32(Vs) + (uint32_t)(lane & 15) * 144u +
                           (uint32_t)((lane >> 4) & 1) * 16u;

    for (int it = 0; it < niter; ++it) {
        const int j0 = it * 64;
        __syncthreads();
#pragma unroll
        for (int i = 0; i < 4; ++i) {
            const int rr = lr + 16 * i;
            unsigned* pk = Ks + rr * QST + pb;
            pk[0] = kreg[i].x; pk[2] = kreg[i].y;
            pk[4] = kreg[i].z; pk[6] = kreg[i].w;
            *reinterpret_cast<uint4*>(Vs + rr * VSTW + c * 4) = vreg[i];
        }
        __syncthreads();

        if (it + 1 < niter) {
            const int jn = j0 + 64;
#pragma unroll
            for (int i = 0; i < 4; ++i) {
                kreg[i] = *reinterpret_cast<const uint4*>(
                    kptr + (size_t)(jn + lr + 16 * i) * N3_ + c * 8);
                vreg[i] = *reinterpret_cast<const uint4*>(
                    vptr + (size_t)(jn + lr + 16 * i) * N3_ + c * 8);
            }
        }

        if (j0 > rowlo + 31) continue;

        // ---- S = Q K^T ----
        float sc[2][8][4] = {};
#pragma unroll
        for (int ks = 0; ks < 4; ++ks) {
            unsigned qa[2][4];
#pragma unroll
            for (int mt = 0; mt < 2; ++mt) {
                const int row = w * 32 + mt * 16 + gid;
                const uint2 lo = *reinterpret_cast<const uint2*>(
                    Qs + row * QST + ks * 8 + 2 * tig);
                const uint2 hi = *reinterpret_cast<const uint2*>(
                    Qs + (row + 8) * QST + ks * 8 + 2 * tig);
                qa[mt][0] = lo.x; qa[mt][1] = hi.x;
                qa[mt][2] = lo.y; qa[mt][3] = hi.y;
            }
#pragma unroll
            for (int nt = 0; nt < 8; ++nt) {
                const uint2 kb = *reinterpret_cast<const uint2*>(
                    Ks + (nt * 8 + gid) * QST + ks * 8 + 2 * tig);
                unsigned bbr[2] = {kb.x, kb.y};
                mma_f16(sc[0][nt], qa[0], bbr);
                mma_f16(sc[1][nt], qa[1], bbr);
            }
        }

        // ---- causal mask ----
#pragma unroll
        for (int mt = 0; mt < 2; ++mt) {
            const int rbase = rowlo + mt * 16;
            if (j0 + 63 > rbase) {
                const int r0 = rbase + gid, r1 = rbase + gid + 8;
#pragma unroll
                for (int nt = 0; nt < 8; ++nt) {
                    const int cc = j0 + nt * 8 + 2 * tig;
                    if (cc > r0)     sc[mt][nt][0] = -1e30f;
                    if (cc + 1 > r0) sc[mt][nt][1] = -1e30f;
                    if (cc > r1)     sc[mt][nt][2] = -1e30f;
                    if (cc + 1 > r1) sc[mt][nt][3] = -1e30f;
                }
            }
        }

        // ---- exp2 + per-lane row sums ----
#pragma unroll
        for (int mt = 0; mt < 2; ++mt) {
            float s0 = 0.0f, s1 = 0.0f;
#pragma unroll
            for (int nt = 0; nt < 8; ++nt) {
                sc[mt][nt][0] = ex2(sc[mt][nt][0]);
                sc[mt][nt][1] = ex2(sc[mt][nt][1]);
                sc[mt][nt][2] = ex2(sc[mt][nt][2]);
                sc[mt][nt][3] = ex2(sc[mt][nt][3]);
                s0 += sc[mt][nt][0] + sc[mt][nt][1];
                s1 += sc[mt][nt][2] + sc[mt][nt][3];
            }
            li[mt][0] += s0;
            li[mt][1] += s1;
        }

        // ---- P fragments: pure cvt ----
        unsigned pa[2][4][4];
#pragma unroll
        for (int mt = 0; mt < 2; ++mt)
#pragma unroll
            for (int ks = 0; ks < 4; ++ks) {
                pa[mt][ks][0] = cvt_h2(sc[mt][2 * ks][0], sc[mt][2 * ks][1]);
                pa[mt][ks][1] = cvt_h2(sc[mt][2 * ks][2], sc[mt][2 * ks][3]);
                pa[mt][ks][2] = cvt_h2(sc[mt][2 * ks + 1][0], sc[mt][2 * ks + 1][1]);
                pa[mt][ks][3] = cvt_h2(sc[mt][2 * ks + 1][2], sc[mt][2 * ks + 1][3]);
            }

        // ---- O += P V ----
#pragma unroll
        for (int dtp = 0; dtp < 4; ++dtp) {
#pragma unroll
            for (int ks = 0; ks < 4; ++ks) {
                unsigned r0, r1, r2, r3;
                asm volatile(
                    "ldmatrix.sync.aligned.m8n8.x4.trans.shared.b16 "
                    "{%0,%1,%2,%3}, [%4];"
                    : "=r"(r0), "=r"(r1), "=r"(r2), "=r"(r3)
                    : "r"(vbase + (uint32_t)ks * 2304u + (uint32_t)dtp * 32u));
                unsigned vb0[2] = {r0, r1};
                unsigned vb1[2] = {r2, r3};
                mma_f16(oc[0][2 * dtp],     pa[0][ks], vb0);
                mma_f16(oc[1][2 * dtp],     pa[1][ks], vb0);
                mma_f16(oc[0][2 * dtp + 1], pa[0][ks], vb1);
                mma_f16(oc[1][2 * dtp + 1], pa[1][ks], vb1);
            }
        }
    }

    // ---- epilogue ----
#pragma unroll
    for (int mt = 0; mt < 2; ++mt) {
        float s0 = li[mt][0], s1 = li[mt][1];
        s0 += __shfl_xor_sync(0xffffffffu, s0, 1);
        s0 += __shfl_xor_sync(0xffffffffu, s0, 2);
        s1 += __shfl_xor_sync(0xffffffffu, s1, 1);
        s1 += __shfl_xor_sync(0xffffffffu, s1, 2);
        const float inv0 = 1.0f / s0;
        const float inv1 = 1.0f / s1;
        const int r0 = q0 + w * 32 + mt * 16 + gid;
        __half* out0 = g_atth + ((size_t)(b * T_ + r0)) * D_ + h * HD_;
        __half* out1 = g_atth + ((size_t)(b * T_ + r0 + 8)) * D_ + h * HD_;
#pragma unroll
        for (int dt = 0; dt < 8; ++dt) {
            const int cc = dt * 8 + 2 * tig;
            *reinterpret_cast<unsigned*>(out0 + cc) =
                cvt_h2(oc[mt][dt][0] * inv0, oc[mt][dt][1] * inv0);
            *reinterpret_cast<unsigned*>(out1 + cc) =
                cvt_h2(oc[mt][dt][2] * inv1, oc[mt][dt][3] * inv1);
        }
    }
}

// ---------------------------------------------------------------------------
extern "C" void kernel_launch(void* const* d_in, const int* in_sizes, int n_in,
                              void* d_out, int out_size) {
    const float* x = nullptr;
    const float* w_qkv = nullptr;
    const float* w_out = nullptr;
    for (int i = 0; i < n_in; ++i) {
        if (in_sizes[i] == M_ * D_)       x = (const float*)d_in[i];
        else if (in_sizes[i] == N3_ * D_) w_qkv = (const float*)d_in[i];
        else if (in_sizes[i] == D_ * D_)  w_out = (const float*)d_in[i];
    }
    float* out = (float*)d_out;

    static __half *hx = nullptr, *hwq = nullptr, *hwo = nullptr;
    static bool attr_set = false;
    if (!attr_set) {
        cudaFuncSetAttribute(gemm_qkv_kernel,
                             cudaFuncAttributeMaxDynamicSharedMemorySize, GEMM_SMEM);
        cudaFuncSetAttribute(gemm_out_kernel,
                             cudaFuncAttributeMaxDynamicSharedMemorySize, GEMM_SMEM);
        cudaGetSymbolAddress((void**)&hx, g_hx);
        cudaGetSymbolAddress((void**)&hwq, g_hwq);
        cudaGetSymbolAddress((void**)&hwo, g_hwo);
        attr_set = true;
    }

    cvt_f2h_kernel<<<1024, 256>>>(x, hx, (M_ * D_) / 4);
    cvt_f2h_kernel<<<512, 256>>>(w_qkv, hwq, (N3_ * D_) / 4);
    cvt_f2h_kernel<<<256, 256>>>(w_out, hwo, (D_ * D_) / 4);

    gemm_qkv_kernel<<<dim3(N3_ / 128, M_ / 128), 256, GEMM_SMEM>>>();
    flash_f16_kernel<<<dim3(B_ * H_, T_ / 128), 128>>>();
    gemm_out_kernel<<<dim3(D_ / 128, M_ / 128), 256, GEMM_SMEM>>>(out);
}

// round 16
// speedup vs baseline: 1.3370x; 1.3370x over previous
#include <cuda_runtime.h>
#include <cuda_fp16.h>
#include <cstdint>

#define B_   2
#define T_   4096
#define D_   512
#define H_   8
#define HD_  64
#define M_   (B_ * T_)
#define N3_  (3 * D_)

__device__ __align__(256) __half g_hx[M_ * D_];
__device__ __align__(256) __half g_hwq[N3_ * D_];
__device__ __align__(256) __half g_hwo[D_ * D_];
__device__ __align__(256) __half g_qkvh[M_ * N3_];
__device__ __align__(256) __half g_atth[M_ * D_];

#define QSCALE 0.180336879f   /* 0.125 * log2(e) */

// ---------------------------------------------------------------------------
// helpers
// ---------------------------------------------------------------------------
__device__ __forceinline__ unsigned cvt_h2(float lo, float hi) {
    unsigned r;
    asm("cvt.rn.f16x2.f32 %0, %1, %2;" : "=r"(r) : "f"(hi), "f"(lo));
    return r;
}
__device__ __forceinline__ float ex2(float x) {
    float r;
    asm("ex2.approx.ftz.f32 %0, %1;" : "=f"(r) : "f"(x));
    return r;
}
__device__ __forceinline__ void mma_f16(float d[4], const unsigned a[4],
                                        const unsigned b[2]) {
    asm volatile(
        "mma.sync.aligned.m16n8k16.row.col.f32.f16.f16.f32 "
        "{%0,%1,%2,%3}, {%4,%5,%6,%7}, {%8,%9}, {%0,%1,%2,%3};\n"
        : "+f"(d[0]), "+f"(d[1]), "+f"(d[2]), "+f"(d[3])
        : "r"(a[0]), "r"(a[1]), "r"(a[2]), "r"(a[3]), "r"(b[0]), "r"(b[1]));
}
__device__ __forceinline__ uint32_t smem_u32(const void* p) {
    uint32_t a;
    asm("{ .reg .u64 t; cvta.to.shared.u64 t, %1; cvt.u32.u64 %0, t; }"
        : "=r"(a) : "l"(p));
    return a;
}
__device__ __forceinline__ void ldsm_x4(unsigned r[4], uint32_t addr) {
    asm volatile("ldmatrix.sync.aligned.m8n8.x4.shared.b16 {%0,%1,%2,%3}, [%4];"
                 : "=r"(r[0]), "=r"(r[1]), "=r"(r[2]), "=r"(r[3]) : "r"(addr));
}
__device__ __forceinline__ void cp16(uint32_t dst, const void* src) {
    asm volatile("cp.async.cg.shared.global [%0], [%1], 16;"
                 :: "r"(dst), "l"(src) : "memory");
}
#define CP_COMMIT() asm volatile("cp.async.commit_group;" ::: "memory")
#define CP_WAIT1()  asm volatile("cp.async.wait_group 1;" ::: "memory")
#define CP_WAIT0()  asm volatile("cp.async.wait_group 0;" ::: "memory")

// ---------------------------------------------------------------------------
// fp32 -> f16 convert (grid-stride)
// ---------------------------------------------------------------------------
__global__ void cvt_f2h_kernel(const float* __restrict__ src,
                               __half* __restrict__ dst, int n4) {
    const int stride = gridDim.x * blockDim.x;
    for (int i = blockIdx.x * blockDim.x + threadIdx.x; i < n4; i += stride) {
        const float4 v = reinterpret_cast<const float4*>(src)[i];
        unsigned* p = reinterpret_cast<unsigned*>(dst) + 2 * i;
        p[0] = cvt_h2(v.x, v.y);
        p[1] = cvt_h2(v.z, v.w);
    }
}

// ---------------------------------------------------------------------------
// NT GEMM, f16, cp.async 2-stage, BK=64, fragments via ldmatrix.x4.
// BM=128, BN=128, 8 warps (4x2), warp tile 32x64, 64 mmas/iter.
// (R15 version — measured 54.4us qkv, best.)
// ---------------------------------------------------------------------------
#define GST2   72
#define GA_H   (128 * GST2)
#define GBUF_H (2 * GA_H)
#define GEMM_SMEM (2 * GBUF_H * 2)    // 73728 B

__device__ __forceinline__ void gemm_cp_tile_h(uint32_t sbase, int s,
                                               const __half* __restrict__ A,
                                               const __half* __restrict__ Bm,
                                               int m0, int n0, int K, int k0,
                                               int lr, int c) {
    const uint32_t da = sbase + (uint32_t)(s * GBUF_H + lr * GST2 + c * 8) * 2u;
    const uint32_t db = da + (uint32_t)GA_H * 2u;
#pragma unroll
    for (int i = 0; i < 4; ++i) {
        cp16(da + (uint32_t)(i * 32 * GST2) * 2u,
             A + (size_t)(m0 + lr + 32 * i) * K + k0 + c * 8);
        cp16(db + (uint32_t)(i * 32 * GST2) * 2u,
             Bm + (size_t)(n0 + lr + 32 * i) * K + k0 + c * 8);
    }
    CP_COMMIT();
}

template <bool HALF_OUT, bool SCALEQ>
__device__ __forceinline__ void gemm_nt_h16(const __half* __restrict__ A,
                                            const __half* __restrict__ Bm,
                                            void* __restrict__ Cv,
                                            int N, int K) {
    extern __shared__ __half hs[];
    const uint32_t sbase = smem_u32(hs);

    const int tid = threadIdx.x;
    const int w = tid >> 5;
    const int lane = tid & 31;
    const int gid = lane >> 2;
    const int tig = lane & 3;
    const int wm = w >> 1;
    const int wn = w & 1;

    const int m0 = blockIdx.y * 128;
    const int n0 = blockIdx.x * 128;

    const int lr = tid >> 3;
    const int c = tid & 7;

    const int niter = K / 64;

    const uint32_t a_u32 = sbase +
        (uint32_t)((wm * 32 + (lane & 15)) * GST2 + ((lane >> 4) << 3)) * 2u;
    const uint32_t b_u32 = sbase + (uint32_t)GA_H * 2u +
        (uint32_t)((wn * 64 + (lane & 7) + ((lane >> 4) << 3)) * GST2 +
                   (((lane >> 3) & 1) << 3)) * 2u;

    gemm_cp_tile_h(sbase, 0, A, Bm, m0, n0, K, 0, lr, c);
    gemm_cp_tile_h(sbase, 1, A, Bm, m0, n0, K, 64, lr, c);

    float acc[2][8][4] = {};

#pragma unroll 1
    for (int it = 0; it < niter; ++it) {
        const int s = it & 1;
        if (it + 1 < niter) { CP_WAIT1(); } else { CP_WAIT0(); }
        __syncthreads();

        const uint32_t soff = (uint32_t)(s * GBUF_H) * 2u;

#pragma unroll
        for (int ks = 0; ks < 4; ++ks) {
            unsigned aa[2][4], bb[4][4];
#pragma unroll
            for (int mt = 0; mt < 2; ++mt)
                ldsm_x4(aa[mt], a_u32 + soff +
                        (uint32_t)(mt * 16 * GST2 + ks * 16) * 2u);
#pragma unroll
            for (int ntp = 0; ntp < 4; ++ntp)
                ldsm_x4(bb[ntp], b_u32 + soff +
                        (uint32_t)(ntp * 16 * GST2 + ks * 16) * 2u);
#pragma unroll
            for (int mt = 0; mt < 2; ++mt)
#pragma unroll
                for (int ntp = 0; ntp < 4; ++ntp) {
                    unsigned b0[2] = {bb[ntp][0], bb[ntp][1]};
                    unsigned b1[2] = {bb[ntp][2], bb[ntp][3]};
                    mma_f16(acc[mt][2 * ntp],     aa[mt], b0);
                    mma_f16(acc[mt][2 * ntp + 1], aa[mt], b1);
                }
        }

        __syncthreads();
        if (it + 2 < niter)
            gemm_cp_tile_h(sbase, s, A, Bm, m0, n0, K, (it + 2) * 64, lr, c);
    }

#pragma unroll
    for (int mt = 0; mt < 2; ++mt) {
        const int r0 = m0 + wm * 32 + mt * 16 + gid;
#pragma unroll
        for (int nt = 0; nt < 8; ++nt) {
            const int cc = n0 + wn * 64 + nt * 8 + 2 * tig;
            if (HALF_OUT) {
                __half* Ch = reinterpret_cast<__half*>(Cv);
                const float sq = (SCALEQ && cc < 512) ? QSCALE : 1.0f;
                *reinterpret_cast<unsigned*>(Ch + (size_t)r0 * N + cc) =
                    cvt_h2(acc[mt][nt][0] * sq, acc[mt][nt][1] * sq);
                *reinterpret_cast<unsigned*>(Ch + (size_t)(r0 + 8) * N + cc) =
                    cvt_h2(acc[mt][nt][2] * sq, acc[mt][nt][3] * sq);
            } else {
                float* Cf = reinterpret_cast<float*>(Cv);
                *reinterpret_cast<float2*>(Cf + (size_t)r0 * N + cc) =
                    make_float2(acc[mt][nt][0], acc[mt][nt][1]);
                *reinterpret_cast<float2*>(Cf + (size_t)(r0 + 8) * N + cc) =
                    make_float2(acc[mt][nt][2], acc[mt][nt][3]);
            }
        }
    }
}

__global__ void __launch_bounds__(256)
gemm_qkv_kernel() {
    gemm_nt_h16<true, true>(g_hx, g_hwq, g_qkvh, N3_, D_);
}

__global__ void __launch_bounds__(256)
gemm_out_kernel(float* __restrict__ out) {
    gemm_nt_h16<false, false>(g_atth, g_hwo, out, D_, D_);
}

// ---------------------------------------------------------------------------
// Flash attention (causal), f16 mma — EXACT R14 version (measured ~115us,
// occ 2, NO spills). 128 threads = 4 warps x 32 q-rows, BM=128, BN=64.
// ---------------------------------------------------------------------------
#define QST 40
#define VSTW 36

__global__ void __launch_bounds__(128, 2) flash_f16_kernel() {
    __shared__ unsigned Qs[128 * QST];
    __shared__ unsigned Ks[64 * QST];
    __shared__ unsigned Vs[64 * VSTW];

    const int tid = threadIdx.x;
    const int w = tid >> 5;
    const int lane = tid & 31;
    const int gid = lane >> 2;
    const int tig = lane & 3;

    const int qt = (int)gridDim.y - 1 - (int)blockIdx.y;
    const int q0 = qt * 128;
    const int bh = blockIdx.x;
    const int b = bh >> 3;
    const int h = bh & 7;

    const __half* qptr = g_qkvh + (size_t)b * T_ * N3_ + h * HD_;
    const __half* kptr = qptr + D_;
    const __half* vptr = qptr + 2 * D_;

    const int lr = tid >> 3;          // 0..15
    const int c = tid & 7;            // 8-half d-chunk
    const int pb = 8 * (c >> 1) + (c & 1);

    // ---- stage Q (already scaled f16; permuted copy) ----
#pragma unroll
    for (int i = 0; i < 8; ++i) {
        const int rr = lr + 16 * i;
        const uint4 v = *reinterpret_cast<const uint4*>(
            qptr + (size_t)(q0 + rr) * N3_ + c * 8);
        unsigned* p = Qs + rr * QST + pb;
        p[0] = v.x; p[2] = v.y; p[4] = v.z; p[6] = v.w;
    }

    uint4 kreg[4], vreg[4];
#pragma unroll
    for (int i = 0; i < 4; ++i) {
        kreg[i] = *reinterpret_cast<const uint4*>(kptr + (size_t)(lr + 16 * i) * N3_ + c * 8);
        vreg[i] = *reinterpret_cast<const uint4*>(vptr + (size_t)(lr + 16 * i) * N3_ + c * 8);
    }

    float oc[2][8][4] = {};
    float li[2][2] = {};

    const int rowlo = q0 + w * 32;
    const int niter = 2 * (qt + 1);

    const uint32_t vbase = smem_u32(Vs) + (uint32_t)(lane & 15) * 144u +
                           (uint32_t)((lane >> 4) & 1) * 16u;

    for (int it = 0; it < niter; ++it) {
        const int j0 = it * 64;
        __syncthreads();
#pragma unroll
        for (int i = 0; i < 4; ++i) {
            const int rr = lr + 16 * i;
            unsigned* pk = Ks + rr * QST + pb;
            pk[0] = kreg[i].x; pk[2] = kreg[i].y;
            pk[4] = kreg[i].z; pk[6] = kreg[i].w;
            *reinterpret_cast<uint4*>(Vs + rr * VSTW + c * 4) = vreg[i];
        }
        __syncthreads();

        if (it + 1 < niter) {
            const int jn = j0 + 64;
#pragma unroll
            for (int i = 0; i < 4; ++i) {
                kreg[i] = *reinterpret_cast<const uint4*>(
                    kptr + (size_t)(jn + lr + 16 * i) * N3_ + c * 8);
                vreg[i] = *reinterpret_cast<const uint4*>(
                    vptr + (size_t)(jn + lr + 16 * i) * N3_ + c * 8);
            }
        }

        if (j0 > rowlo + 31) continue;

        // ---- S = Q K^T ----
        float sc[2][8][4] = {};
#pragma unroll
        for (int ks = 0; ks < 4; ++ks) {
            unsigned qa[2][4];
#pragma unroll
            for (int mt = 0; mt < 2; ++mt) {
                const int row = w * 32 + mt * 16 + gid;
                const uint2 lo = *reinterpret_cast<const uint2*>(
                    Qs + row * QST + ks * 8 + 2 * tig);
                const uint2 hi = *reinterpret_cast<const uint2*>(
                    Qs + (row + 8) * QST + ks * 8 + 2 * tig);
                qa[mt][0] = lo.x; qa[mt][1] = hi.x;
                qa[mt][2] = lo.y; qa[mt][3] = hi.y;
            }
#pragma unroll
            for (int nt = 0; nt < 8; ++nt) {
                const uint2 kb = *reinterpret_cast<const uint2*>(
                    Ks + (nt * 8 + gid) * QST + ks * 8 + 2 * tig);
                unsigned bbr[2] = {kb.x, kb.y};
                mma_f16(sc[0][nt], qa[0], bbr);
                mma_f16(sc[1][nt], qa[1], bbr);
            }
        }

        // ---- causal mask ----
#pragma unroll
        for (int mt = 0; mt < 2; ++mt) {
            const int rbase = rowlo + mt * 16;
            if (j0 + 63 > rbase) {
                const int r0 = rbase + gid, r1 = rbase + gid + 8;
#pragma unroll
                for (int nt = 0; nt < 8; ++nt) {
                    const int cc = j0 + nt * 8 + 2 * tig;
                    if (cc > r0)     sc[mt][nt][0] = -1e30f;
                    if (cc + 1 > r0) sc[mt][nt][1] = -1e30f;
                    if (cc > r1)     sc[mt][nt][2] = -1e30f;
                    if (cc + 1 > r1) sc[mt][nt][3] = -1e30f;
                }
            }
        }

        // ---- exp2 + per-lane row sums ----
#pragma unroll
        for (int mt = 0; mt < 2; ++mt) {
            float s0 = 0.0f, s1 = 0.0f;
#pragma unroll
            for (int nt = 0; nt < 8; ++nt) {
                sc[mt][nt][0] = ex2(sc[mt][nt][0]);
                sc[mt][nt][1] = ex2(sc[mt][nt][1]);
                sc[mt][nt][2] = ex2(sc[mt][nt][2]);
                sc[mt][nt][3] = ex2(sc[mt][nt][3]);
                s0 += sc[mt][nt][0] + sc[mt][nt][1];
                s1 += sc[mt][nt][2] + sc[mt][nt][3];
            }
            li[mt][0] += s0;
            li[mt][1] += s1;
        }

        // ---- P fragments: pure cvt ----
        unsigned pa[2][4][4];
#pragma unroll
        for (int mt = 0; mt < 2; ++mt)
#pragma unroll
            for (int ks = 0; ks < 4; ++ks) {
                pa[mt][ks][0] = cvt_h2(sc[mt][2 * ks][0], sc[mt][2 * ks][1]);
                pa[mt][ks][1] = cvt_h2(sc[mt][2 * ks][2], sc[mt][2 * ks][3]);
                pa[mt][ks][2] = cvt_h2(sc[mt][2 * ks + 1][0], sc[mt][2 * ks + 1][1]);
                pa[mt][ks][3] = cvt_h2(sc[mt][2 * ks + 1][2], sc[mt][2 * ks + 1][3]);
            }

        // ---- O += P V ----
#pragma unroll
        for (int dtp = 0; dtp < 4; ++dtp) {
#pragma unroll
            for (int ks = 0; ks < 4; ++ks) {
                unsigned r0, r1, r2, r3;
                asm volatile(
                    "ldmatrix.sync.aligned.m8n8.x4.trans.shared.b16 "
                    "{%0,%1,%2,%3}, [%4];"
                    : "=r"(r0), "=r"(r1), "=r"(r2), "=r"(r3)
                    : "r"(vbase + (uint32_t)ks * 2304u + (uint32_t)dtp * 32u));
                unsigned vb0[2] = {r0, r1};
                unsigned vb1[2] = {r2, r3};
                mma_f16(oc[0][2 * dtp],     pa[0][ks], vb0);
                mma_f16(oc[1][2 * dtp],     pa[1][ks], vb0);
                mma_f16(oc[0][2 * dtp + 1], pa[0][ks], vb1);
                mma_f16(oc[1][2 * dtp + 1], pa[1][ks], vb1);
            }
        }
    }

    // ---- epilogue ----
#pragma unroll
    for (int mt = 0; mt < 2; ++mt) {
        float s0 = li[mt][0], s1 = li[mt][1];
        s0 += __shfl_xor_sync(0xffffffffu, s0, 1);
        s0 += __shfl_xor_sync(0xffffffffu, s0, 2);
        s1 += __shfl_xor_sync(0xffffffffu, s1, 1);
        s1 += __shfl_xor_sync(0xffffffffu, s1, 2);
        const float inv0 = 1.0f / s0;
        const float inv1 = 1.0f / s1;
        const int r0 = q0 + w * 32 + mt * 16 + gid;
        __half* out0 = g_atth + ((size_t)(b * T_ + r0)) * D_ + h * HD_;
        __half* out1 = g_atth + ((size_t)(b * T_ + r0 + 8)) * D_ + h * HD_;
#pragma unroll
        for (int dt = 0; dt < 8; ++dt) {
            const int cc = dt * 8 + 2 * tig;
            *reinterpret_cast<unsigned*>(out0 + cc) =
                cvt_h2(oc[mt][dt][0] * inv0, oc[mt][dt][1] * inv0);
            *reinterpret_cast<unsigned*>(out1 + cc) =
                cvt_h2(oc[mt][dt][2] * inv1, oc[mt][dt][3] * inv1);
        }
    }
}

// ---------------------------------------------------------------------------
extern "C" void kernel_launch(void* const* d_in, const int* in_sizes, int n_in,
                              void* d_out, int out_size) {
    const float* x = nullptr;
    const float* w_qkv = nullptr;
    const float* w_out = nullptr;
    for (int i = 0; i < n_in; ++i) {
        if (in_sizes[i] == M_ * D_)       x = (const float*)d_in[i];
        else if (in_sizes[i] == N3_ * D_) w_qkv = (const float*)d_in[i];
        else if (in_sizes[i] == D_ * D_)  w_out = (const float*)d_in[i];
    }
    float* out = (float*)d_out;

    static __half *hx = nullptr, *hwq = nullptr, *hwo = nullptr;
    static bool attr_set = false;
    if (!attr_set) {
        cudaFuncSetAttribute(gemm_qkv_kernel,
                             cudaFuncAttributeMaxDynamicSharedMemorySize, GEMM_SMEM);
        cudaFuncSetAttribute(gemm_out_kernel,
                             cudaFuncAttributeMaxDynamicSharedMemorySize, GEMM_SMEM);
        cudaGetSymbolAddress((void**)&hx, g_hx);
        cudaGetSymbolAddress((void**)&hwq, g_hwq);
        cudaGetSymbolAddress((void**)&hwo, g_hwo);
        attr_set = true;
    }

    cvt_f2h_kernel<<<1024, 256>>>(x, hx, (M_ * D_) / 4);
    cvt_f2h_kernel<<<512, 256>>>(w_qkv, hwq, (N3_ * D_) / 4);
    cvt_f2h_kernel<<<256, 256>>>(w_out, hwo, (D_ * D_) / 4);

    gemm_qkv_kernel<<<dim3(N3_ / 128, M_ / 128), 256, GEMM_SMEM>>>();
    flash_f16_kernel<<<dim3(B_ * H_, T_ / 128), 128>>>();
    gemm_out_kernel<<<dim3(D_ / 128, M_ / 128), 256, GEMM_SMEM>>>(out);
}